// round 6
// baseline (speedup 1.0000x reference)
#include <cuda_runtime.h>
#include <math.h>

#define NG 512
#define IW 256
#define IH 256
#define HW (IW*IH)

// Depth-sorted per-gaussian parameters, 16 floats each (64B, float4-friendly):
// [0]=mx [1]=my [2]=i00 [3]=i01 [4]=i11 [5]=op [6]=r [7]=g [8]=b [9]=dep
// [10],[11]=pad  [12]=xlo [13]=xhi [14]=ylo [15]=yhi
__device__ float g_sorted[NG][16];

__global__ void __launch_bounds__(NG, 1)
prep_sort_kernel(const float* __restrict__ xyz,
                 const float* __restrict__ opa,
                 const float* __restrict__ feat,
                 const float* __restrict__ cov,
                 const float* __restrict__ Km,
                 const float* __restrict__ w2c,
                 float* __restrict__ radii_out)
{
    const int i = threadIdx.x;

    // Camera matrices (broadcast loads)
    float R[3][3], t[3], Kc[3][3];
    #pragma unroll
    for (int r = 0; r < 3; r++) {
        #pragma unroll
        for (int c = 0; c < 3; c++) {
            R[r][c]  = w2c[r*4 + c];
            Kc[r][c] = Km[r*3 + c];
        }
        t[r] = w2c[r*4 + 3];
    }

    const float px = xyz[i*3+0], py = xyz[i*3+1], pz = xyz[i*3+2];

    // xyz_cam = R @ p + t
    const float xc = R[0][0]*px + R[0][1]*py + R[0][2]*pz + t[0];
    const float yc = R[1][0]*px + R[1][1]*py + R[1][2]*pz + t[1];
    const float zc = R[2][0]*px + R[2][1]*py + R[2][2]*pz + t[2];
    const float depth = zc;

    // Projection: xy_h = K @ xyz_cam; xy = xy_h[:2]/max(xy_h[2],1e-8)
    const float hx = Kc[0][0]*xc + Kc[0][1]*yc + Kc[0][2]*zc;
    const float hy = Kc[1][0]*xc + Kc[1][1]*yc + Kc[1][2]*zc;
    const float hz = Kc[2][0]*xc + Kc[2][1]*yc + Kc[2][2]*zc;
    const float denom = fmaxf(hz, 1e-8f);
    const float mx = hx / denom;
    const float my = hy / denom;

    const float margin = 256.0f;
    const bool visible = (depth > 0.01f)
        && (mx > -margin) && (mx < (float)IW + margin)
        && (my > -margin) && (my < (float)IH + margin);

    // cam_pos = inv(w2c)[:3,3]  (rigid inverse: -R^T t; w2c is eye(4) here)
    const float cpx = -(R[0][0]*t[0] + R[1][0]*t[1] + R[2][0]*t[2]);
    const float cpy = -(R[0][1]*t[0] + R[1][1]*t[1] + R[2][1]*t[2]);
    const float cpz = -(R[0][2]*t[0] + R[1][2]*t[1] + R[2][2]*t[2]);

    // View direction
    float vx = px - cpx, vy = py - cpy, vz = pz - cpz;
    const float nrm = sqrtf(vx*vx + vy*vy + vz*vz);
    const float inv_nrm = 1.0f / fmaxf(nrm, 1e-12f);
    vx *= inv_nrm; vy *= inv_nrm; vz *= inv_nrm;

    // SH basis, degree 3 (16 coeffs), matching reference signs
    const float xx = vx*vx, yy = vy*vy, zz = vz*vz;
    const float xy_ = vx*vy, yz_ = vy*vz, xz_ = vx*vz;
    float B[16];
    B[0]  = 0.28209479177387814f;
    B[1]  = -0.4886025119029199f * vy;
    B[2]  =  0.4886025119029199f * vz;
    B[3]  = -0.4886025119029199f * vx;
    B[4]  =  1.0925484305920792f * xy_;
    B[5]  = -1.0925484305920792f * yz_;
    B[6]  =  0.31539156525252005f * (2.0f*zz - xx - yy);
    B[7]  = -1.0925484305920792f * xz_;
    B[8]  =  0.5462742152960396f * (xx - yy);
    B[9]  = -0.5900435899266435f * vy * (3.0f*xx - yy);
    B[10] =  2.890611442640554f  * xy_ * vz;
    B[11] = -0.4570457994644658f * vy * (4.0f*zz - xx - yy);
    B[12] =  0.3731763325901154f * vz * (2.0f*zz - 3.0f*xx - 3.0f*yy);
    B[13] = -0.4570457994644658f * vx * (4.0f*zz - xx - yy);
    B[14] =  1.445305721320277f  * vz * (xx - yy);
    B[15] = -0.5900435899266435f * vx * (xx - 3.0f*yy);

    float rgb[3];
    #pragma unroll
    for (int c = 0; c < 3; c++) {
        float s = 0.0f;
        #pragma unroll
        for (int j = 0; j < 16; j++)
            s += B[j] * feat[i*48 + j*3 + c];
        rgb[c] = fminf(fmaxf(s + 0.5f, 0.0f), 1.0f);
    }

    // 2D covariance: J = [[fx/tz,0,-fx*xc/tz2],[0,fy/tz,-fy*yc/tz2],[0,..]]
    const float fx = Kc[0][0], fy = Kc[1][1];
    const float tz = fmaxf(zc, 1e-8f);
    const float tz2 = tz*tz;
    const float J00 = fx/tz, J02 = -fx*xc/tz2;
    const float J11 = fy/tz, J12 = -fy*yc/tz2;

    float T0[3], T1[3];
    #pragma unroll
    for (int c = 0; c < 3; c++) {
        T0[c] = J00*R[0][c] + J02*R[2][c];
        T1[c] = J11*R[1][c] + J12*R[2][c];
    }
    // v0 = Sigma @ T0, v1 = Sigma @ T1
    float S[3][3];
    #pragma unroll
    for (int r = 0; r < 3; r++)
        #pragma unroll
        for (int c = 0; c < 3; c++)
            S[r][c] = cov[i*9 + r*3 + c];
    float v0[3], v1[3];
    #pragma unroll
    for (int r = 0; r < 3; r++) {
        v0[r] = S[r][0]*T0[0] + S[r][1]*T0[1] + S[r][2]*T0[2];
        v1[r] = S[r][0]*T1[0] + S[r][1]*T1[1] + S[r][2]*T1[2];
    }
    const float a  = T0[0]*v0[0] + T0[1]*v0[1] + T0[2]*v0[2] + 0.3f;
    const float b  = T1[0]*v0[0] + T1[1]*v0[1] + T1[2]*v0[2];
    const float d  = T1[0]*v1[0] + T1[1]*v1[1] + T1[2]*v1[2] + 0.3f;

    const float det = a*d - b*b;
    const float tr  = a + d;
    const float lam = 0.5f * (tr + sqrtf(fmaxf(tr*tr - 4.0f*det, 0.0f)));
    const float radf = 3.0f * sqrtf(fmaxf(lam, 1e-8f));

    radii_out[i] = visible ? radf : 0.0f;

    const float detc = fmaxf(det, 1e-10f);
    const float i00 =  d / detc;
    const float i01 = -b / detc;
    const float i11 =  a / detc;

    // Bounding box (exact reference semantics: floor(clip(...)))
    const float rad = fmaxf(radf, 1.0f);
    float xlo, xhi, ylo, yhi;
    if (visible) {
        xlo = floorf(fminf(fmaxf(mx - rad,        0.0f), (float)IW));
        xhi = floorf(fminf(fmaxf(mx + rad + 1.0f, 0.0f), (float)IW));
        ylo = floorf(fminf(fmaxf(my - rad,        0.0f), (float)IH));
        yhi = floorf(fminf(fmaxf(my + rad + 1.0f, 0.0f), (float)IH));
    } else {
        xlo = xhi = ylo = yhi = 0.0f;  // empty box: never composited
    }

    // --- Stable depth sort (matches jnp.argsort(where(vis, depth, inf))) ---
    __shared__ float skey[NG];
    const float key = visible ? depth : __int_as_float(0x7f800000);  // +inf
    skey[i] = key;
    __syncthreads();

    int rank = 0;
    #pragma unroll 8
    for (int j = 0; j < NG; j++) {
        const float kj = skey[j];
        rank += (kj < key) || ((kj == key) && (j < i));
    }

    float* dst = g_sorted[rank];
    dst[0] = mx;   dst[1] = my;   dst[2] = i00;  dst[3] = i01;
    dst[4] = i11;  dst[5] = opa[i]; dst[6] = rgb[0]; dst[7] = rgb[1];
    dst[8] = rgb[2]; dst[9] = depth; dst[10] = 0.0f; dst[11] = 0.0f;
    dst[12] = xlo; dst[13] = xhi;  dst[14] = ylo;  dst[15] = yhi;
}

__global__ void __launch_bounds__(256, 1)
render_kernel(const float* __restrict__ bg, float* __restrict__ out)
{
    __shared__ float s_par[NG][16];   // 32 KB
    __shared__ int   s_cnt;

    const int tx0 = blockIdx.x * 16;
    const int ty0 = blockIdx.y * 16;
    const int tid = threadIdx.y * 16 + threadIdx.x;

    // --- Warp 0: order-preserving compaction of sorted gaussians vs tile ---
    if (tid < 32) {
        const int lane = tid;
        const float ftx0 = (float)tx0, ftx1 = (float)(tx0 + 15);
        const float fty0 = (float)ty0, fty1 = (float)(ty0 + 15);
        int base = 0;
        for (int c = 0; c < NG; c += 32) {
            const int g = c + lane;
            const float4 bb = *(const float4*)&g_sorted[g][12]; // xlo,xhi,ylo,yhi
            const bool hit = (bb.y > ftx0) && (bb.x <= ftx1) &&
                             (bb.w > fty0) && (bb.z <= fty1);
            const unsigned m = __ballot_sync(0xffffffffu, hit);
            if (hit) {
                const int pos = base + __popc(m & ((1u << lane) - 1u));
                const float4* s = (const float4*)g_sorted[g];
                float4* dd = (float4*)s_par[pos];
                dd[0] = s[0]; dd[1] = s[1]; dd[2] = s[2]; dd[3] = s[3];
            }
            base += __popc(m);
        }
        if (lane == 0) s_cnt = base;
    }
    __syncthreads();

    // --- Per-pixel front-to-back compositing over the tile's list ---
    const int n = s_cnt;
    const float gx = (float)(tx0 + threadIdx.x);
    const float gy = (float)(ty0 + threadIdx.y);

    float T = 1.0f, c0 = 0.0f, c1 = 0.0f, c2 = 0.0f, dsum = 0.0f;

    for (int k = 0; k < n; k++) {
        const float4* p = (const float4*)s_par[k];  // broadcast across warp
        const float4 bb = p[3];
        if (gx >= bb.x && gx < bb.y && gy >= bb.z && gy < bb.w) {
            const float4 a0 = p[0];   // mx,my,i00,i01
            const float4 a1 = p[1];   // i11,op,r,g
            const float4 a2 = p[2];   // b,dep,-,-
            const float dx = gx - a0.x;
            const float dy = gy - a0.y;
            const float maha = a0.z*dx*dx + 2.0f*a0.w*dx*dy + a1.x*dy*dy;
            const float w = __expf(-0.5f * maha);
            const float alpha = fminf(a1.y * w, 0.99f);
            const float tc = T * alpha;
            c0   += tc * a1.z;
            c1   += tc * a1.w;
            c2   += tc * a2.x;
            dsum += tc * a2.y;
            T *= (1.0f - alpha);
            if (T < 1e-7f) break;
        }
    }

    const int idx = (ty0 + threadIdx.y) * IW + (tx0 + threadIdx.x);
    out[0*HW + idx] = c0 + bg[0] * T;
    out[1*HW + idx] = c1 + bg[1] * T;
    out[2*HW + idx] = c2 + bg[2] * T;
    out[3*HW + idx] = dsum;
    out[4*HW + idx] = 1.0f - T;
}

extern "C" void kernel_launch(void* const* d_in, const int* in_sizes, int n_in,
                              void* d_out, int out_size)
{
    const float* xyz  = (const float*)d_in[0];
    const float* opa  = (const float*)d_in[1];
    const float* feat = (const float*)d_in[2];
    const float* cov  = (const float*)d_in[3];
    const float* Km   = (const float*)d_in[4];
    const float* w2c  = (const float*)d_in[5];
    const float* bg   = (const float*)d_in[6];
    float* out = (float*)d_out;

    // radii live at the tail of the output: after 5 HxW planes
    prep_sort_kernel<<<1, NG>>>(xyz, opa, feat, cov, Km, w2c, out + 5*HW);

    dim3 grid(IW/16, IH/16);
    dim3 block(16, 16);
    render_kernel<<<grid, block>>>(bg, out);
}

// round 7
// speedup vs baseline: 2.8333x; 2.8333x over previous
#include <cuda_runtime.h>
#include <math.h>

#define NG 512
#define IW 256
#define IH 256
#define HW (IW*IH)

// Per-block-resident gaussian record (16 floats):
// [0]=mx [1]=my [2]=i00 [3]=i01 [4]=i11 [5]=op [6]=r [7]=g [8]=b [9]=dep
// [10]=orig_idx (as float)  [11]=pad  [12]=xlo [13]=xhi [14]=ylo [15]=yhi

__global__ void __launch_bounds__(256, 2)
fused_render_kernel(const float* __restrict__ xyz,
                    const float* __restrict__ opa,
                    const float* __restrict__ feat,
                    const float* __restrict__ cov,
                    const float* __restrict__ Km,
                    const float* __restrict__ w2c,
                    const float* __restrict__ bg,
                    float* __restrict__ out)
{
    __shared__ float s_par[NG][16];   // 32 KB (worst case: all gaussians hit)
    __shared__ int   s_ord[NG];       // 2 KB
    __shared__ int   s_cnt;

    const int tid = threadIdx.y * 16 + threadIdx.x;
    const int tx0 = blockIdx.x * 16;
    const int ty0 = blockIdx.y * 16;
    const bool is_block0 = (blockIdx.x == 0 && blockIdx.y == 0);

    if (tid == 0) s_cnt = 0;
    __syncthreads();

    // Camera matrices (broadcast loads, L1/L2 hit)
    float R[3][3], t[3], Kc[3][3];
    #pragma unroll
    for (int r = 0; r < 3; r++) {
        #pragma unroll
        for (int c = 0; c < 3; c++) {
            R[r][c]  = w2c[r*4 + c];
            Kc[r][c] = Km[r*3 + c];
        }
        t[r] = w2c[r*4 + 3];
    }
    const float fx = Kc[0][0], fy = Kc[1][1];
    // cam_pos = -R^T t (rigid inverse of w2c)
    const float cpx = -(R[0][0]*t[0] + R[1][0]*t[1] + R[2][0]*t[2]);
    const float cpy = -(R[0][1]*t[0] + R[1][1]*t[1] + R[2][1]*t[2]);
    const float cpz = -(R[0][2]*t[0] + R[1][2]*t[1] + R[2][2]*t[2]);

    const float ftx0 = (float)tx0, ftx1 = (float)(tx0 + 15);
    const float fty0 = (float)ty0, fty1 = (float)(ty0 + 15);

    // ---- Phase 1: per-block prep of all gaussians (2 per thread) ----
    #pragma unroll
    for (int gi = 0; gi < 2; gi++) {
        const int i = tid + gi * 256;

        const float px = xyz[i*3+0], py = xyz[i*3+1], pz = xyz[i*3+2];

        const float xc = R[0][0]*px + R[0][1]*py + R[0][2]*pz + t[0];
        const float yc = R[1][0]*px + R[1][1]*py + R[1][2]*pz + t[1];
        const float zc = R[2][0]*px + R[2][1]*py + R[2][2]*pz + t[2];
        const float depth = zc;

        const float hx = Kc[0][0]*xc + Kc[0][1]*yc + Kc[0][2]*zc;
        const float hy = Kc[1][0]*xc + Kc[1][1]*yc + Kc[1][2]*zc;
        const float hz = Kc[2][0]*xc + Kc[2][1]*yc + Kc[2][2]*zc;
        const float denom = fmaxf(hz, 1e-8f);
        const float mx = hx / denom;
        const float my = hy / denom;

        const float margin = 256.0f;
        const bool visible = (depth > 0.01f)
            && (mx > -margin) && (mx < (float)IW + margin)
            && (my > -margin) && (my < (float)IH + margin);

        // 2D covariance (needed for radii output even when off-tile)
        const float tz = fmaxf(zc, 1e-8f);
        const float tz2 = tz*tz;
        const float J00 = fx/tz, J02 = -fx*xc/tz2;
        const float J11 = fy/tz, J12 = -fy*yc/tz2;

        float T0[3], T1[3];
        #pragma unroll
        for (int c = 0; c < 3; c++) {
            T0[c] = J00*R[0][c] + J02*R[2][c];
            T1[c] = J11*R[1][c] + J12*R[2][c];
        }
        float S[3][3];
        #pragma unroll
        for (int r = 0; r < 3; r++)
            #pragma unroll
            for (int c = 0; c < 3; c++)
                S[r][c] = cov[i*9 + r*3 + c];
        float v0[3], v1[3];
        #pragma unroll
        for (int r = 0; r < 3; r++) {
            v0[r] = S[r][0]*T0[0] + S[r][1]*T0[1] + S[r][2]*T0[2];
            v1[r] = S[r][0]*T1[0] + S[r][1]*T1[1] + S[r][2]*T1[2];
        }
        const float a  = T0[0]*v0[0] + T0[1]*v0[1] + T0[2]*v0[2] + 0.3f;
        const float b  = T1[0]*v0[0] + T1[1]*v0[1] + T1[2]*v0[2];
        const float d  = T1[0]*v1[0] + T1[1]*v1[1] + T1[2]*v1[2] + 0.3f;

        const float det = a*d - b*b;
        const float tr  = a + d;
        const float lam = 0.5f * (tr + sqrtf(fmaxf(tr*tr - 4.0f*det, 0.0f)));
        const float radf = 3.0f * sqrtf(fmaxf(lam, 1e-8f));

        if (is_block0)
            out[5*HW + i] = visible ? radf : 0.0f;

        if (!visible) continue;

        // bbox (exact reference floor(clip()) semantics)
        const float rad = fmaxf(radf, 1.0f);
        const float xlo = floorf(fminf(fmaxf(mx - rad,        0.0f), (float)IW));
        const float xhi = floorf(fminf(fmaxf(mx + rad + 1.0f, 0.0f), (float)IW));
        const float ylo = floorf(fminf(fmaxf(my - rad,        0.0f), (float)IH));
        const float yhi = floorf(fminf(fmaxf(my + rad + 1.0f, 0.0f), (float)IH));

        // tile overlap test
        if (!(xhi > ftx0 && xlo <= ftx1 && yhi > fty0 && ylo <= fty1))
            continue;

        // conic
        const float detc = fmaxf(det, 1e-10f);
        const float i00 =  d / detc;
        const float i01 = -b / detc;
        const float i11 =  a / detc;

        // view direction + SH->RGB (only for gaussians that hit this tile)
        float vx = px - cpx, vy = py - cpy, vz = pz - cpz;
        const float inv_nrm = 1.0f / fmaxf(sqrtf(vx*vx + vy*vy + vz*vz), 1e-12f);
        vx *= inv_nrm; vy *= inv_nrm; vz *= inv_nrm;

        const float xx = vx*vx, yy = vy*vy, zz = vz*vz;
        const float xy_ = vx*vy, yz_ = vy*vz, xz_ = vx*vz;
        float B[16];
        B[0]  = 0.28209479177387814f;
        B[1]  = -0.4886025119029199f * vy;
        B[2]  =  0.4886025119029199f * vz;
        B[3]  = -0.4886025119029199f * vx;
        B[4]  =  1.0925484305920792f * xy_;
        B[5]  = -1.0925484305920792f * yz_;
        B[6]  =  0.31539156525252005f * (2.0f*zz - xx - yy);
        B[7]  = -1.0925484305920792f * xz_;
        B[8]  =  0.5462742152960396f * (xx - yy);
        B[9]  = -0.5900435899266435f * vy * (3.0f*xx - yy);
        B[10] =  2.890611442640554f  * xy_ * vz;
        B[11] = -0.4570457994644658f * vy * (4.0f*zz - xx - yy);
        B[12] =  0.3731763325901154f * vz * (2.0f*zz - 3.0f*xx - 3.0f*yy);
        B[13] = -0.4570457994644658f * vx * (4.0f*zz - xx - yy);
        B[14] =  1.445305721320277f  * vz * (xx - yy);
        B[15] = -0.5900435899266435f * vx * (xx - 3.0f*yy);

        float rgb[3];
        #pragma unroll
        for (int c = 0; c < 3; c++) {
            float s = 0.0f;
            #pragma unroll
            for (int j = 0; j < 16; j++)
                s += B[j] * feat[i*48 + j*3 + c];
            rgb[c] = fminf(fmaxf(s + 0.5f, 0.0f), 1.0f);
        }

        const int pos = atomicAdd(&s_cnt, 1);
        float* dst = s_par[pos];
        dst[0] = mx;     dst[1] = my;     dst[2]  = i00;   dst[3]  = i01;
        dst[4] = i11;    dst[5] = opa[i]; dst[6]  = rgb[0]; dst[7] = rgb[1];
        dst[8] = rgb[2]; dst[9] = depth;  dst[10] = (float)i; dst[11] = 0.0f;
        dst[12] = xlo;   dst[13] = xhi;   dst[14] = ylo;   dst[15] = yhi;
    }
    __syncthreads();

    // ---- Phase 2: stable rank sort of this tile's list by (depth, idx) ----
    const int n = s_cnt;
    for (int tt = tid; tt < n; tt += 256) {
        const float dep = s_par[tt][9];
        const float id  = s_par[tt][10];
        int rank = 0;
        for (int j = 0; j < n; j++) {
            const float dj = s_par[j][9];
            const float ij = s_par[j][10];
            rank += (dj < dep) || ((dj == dep) && (ij < id));
        }
        s_ord[rank] = tt;
    }
    __syncthreads();

    // ---- Phase 3: per-pixel front-to-back compositing ----
    const float gx = (float)(tx0 + threadIdx.x);
    const float gy = (float)(ty0 + threadIdx.y);

    float T = 1.0f, c0 = 0.0f, c1 = 0.0f, c2 = 0.0f, dsum = 0.0f;

    for (int k = 0; k < n; k++) {
        const float4* p = (const float4*)s_par[s_ord[k]];  // broadcast reads
        const float4 bb = p[3];
        if (gx >= bb.x && gx < bb.y && gy >= bb.z && gy < bb.w) {
            const float4 a0 = p[0];   // mx,my,i00,i01
            const float4 a1 = p[1];   // i11,op,r,g
            const float4 a2 = p[2];   // b,dep,idx,pad
            const float dx = gx - a0.x;
            const float dy = gy - a0.y;
            const float maha = a0.z*dx*dx + 2.0f*a0.w*dx*dy + a1.x*dy*dy;
            const float w = __expf(-0.5f * maha);
            const float alpha = fminf(a1.y * w, 0.99f);
            const float tc = T * alpha;
            c0   += tc * a1.z;
            c1   += tc * a1.w;
            c2   += tc * a2.x;
            dsum += tc * a2.y;
            T *= (1.0f - alpha);
            if (T < 1e-7f) break;
        }
    }

    const int idx = (ty0 + threadIdx.y) * IW + (tx0 + threadIdx.x);
    out[0*HW + idx] = c0 + bg[0] * T;
    out[1*HW + idx] = c1 + bg[1] * T;
    out[2*HW + idx] = c2 + bg[2] * T;
    out[3*HW + idx] = dsum;
    out[4*HW + idx] = 1.0f - T;
}

extern "C" void kernel_launch(void* const* d_in, const int* in_sizes, int n_in,
                              void* d_out, int out_size)
{
    const float* xyz  = (const float*)d_in[0];
    const float* opa  = (const float*)d_in[1];
    const float* feat = (const float*)d_in[2];
    const float* cov  = (const float*)d_in[3];
    const float* Km   = (const float*)d_in[4];
    const float* w2c  = (const float*)d_in[5];
    const float* bg   = (const float*)d_in[6];
    float* out = (float*)d_out;

    dim3 grid(IW/16, IH/16);
    dim3 block(16, 16);
    fused_render_kernel<<<grid, block>>>(xyz, opa, feat, cov, Km, w2c, bg, out);
}

// round 8
// speedup vs baseline: 3.0080x; 1.0617x over previous
#include <cuda_runtime.h>
#include <math.h>

#define NG 512
#define IW 256
#define IH 256
#define HW (IW*IH)
#define TW 32   // tile width
#define TH 16   // tile height

// Per-block-resident gaussian record (16 floats):
// [0]=mx [1]=my [2]=i00 [3]=i01 [4]=i11 [5]=op [6]=r [7]=g [8]=b [9]=dep
// [10]=orig_idx (as float)  [11]=pad  [12]=xlo [13]=xhi [14]=ylo [15]=yhi

__global__ void __launch_bounds__(TW*TH, 1)
fused_render_kernel(const float* __restrict__ xyz,
                    const float* __restrict__ opa,
                    const float* __restrict__ feat,
                    const float* __restrict__ cov,
                    const float* __restrict__ Km,
                    const float* __restrict__ w2c,
                    const float* __restrict__ bg,
                    float* __restrict__ out)
{
    __shared__ float s_par[NG][16];   // 32 KB (worst case: all gaussians hit)
    __shared__ int   s_ord[NG];       // 2 KB
    __shared__ int   s_cnt;

    const int tid = threadIdx.y * TW + threadIdx.x;
    const int tx0 = blockIdx.x * TW;
    const int ty0 = blockIdx.y * TH;
    const bool is_block0 = (blockIdx.x == 0 && blockIdx.y == 0);

    if (tid == 0) s_cnt = 0;
    __syncthreads();

    // Camera matrices (broadcast loads, L1/L2 hit)
    float R[3][3], t[3], Kc[3][3];
    #pragma unroll
    for (int r = 0; r < 3; r++) {
        #pragma unroll
        for (int c = 0; c < 3; c++) {
            R[r][c]  = w2c[r*4 + c];
            Kc[r][c] = Km[r*3 + c];
        }
        t[r] = w2c[r*4 + 3];
    }
    const float fx = Kc[0][0], fy = Kc[1][1];
    // cam_pos = -R^T t (rigid inverse of w2c)
    const float cpx = -(R[0][0]*t[0] + R[1][0]*t[1] + R[2][0]*t[2]);
    const float cpy = -(R[0][1]*t[0] + R[1][1]*t[1] + R[2][1]*t[2]);
    const float cpz = -(R[0][2]*t[0] + R[1][2]*t[1] + R[2][2]*t[2]);

    const float ftx0 = (float)tx0, ftx1 = (float)(tx0 + TW - 1);
    const float fty0 = (float)ty0, fty1 = (float)(ty0 + TH - 1);

    // ---- Phase 1: per-block prep, 1 gaussian per thread ----
    {
        const int i = tid;

        const float px = xyz[i*3+0], py = xyz[i*3+1], pz = xyz[i*3+2];

        const float xc = R[0][0]*px + R[0][1]*py + R[0][2]*pz + t[0];
        const float yc = R[1][0]*px + R[1][1]*py + R[1][2]*pz + t[1];
        const float zc = R[2][0]*px + R[2][1]*py + R[2][2]*pz + t[2];
        const float depth = zc;

        const float hx = Kc[0][0]*xc + Kc[0][1]*yc + Kc[0][2]*zc;
        const float hy = Kc[1][0]*xc + Kc[1][1]*yc + Kc[1][2]*zc;
        const float hz = Kc[2][0]*xc + Kc[2][1]*yc + Kc[2][2]*zc;
        const float denom = fmaxf(hz, 1e-8f);
        const float mx = hx / denom;
        const float my = hy / denom;

        const float margin = 256.0f;
        const bool visible = (depth > 0.01f)
            && (mx > -margin) && (mx < (float)IW + margin)
            && (my > -margin) && (my < (float)IH + margin);

        // 2D covariance
        const float tz = fmaxf(zc, 1e-8f);
        const float tz2 = tz*tz;
        const float J00 = fx/tz, J02 = -fx*xc/tz2;
        const float J11 = fy/tz, J12 = -fy*yc/tz2;

        float T0[3], T1[3];
        #pragma unroll
        for (int c = 0; c < 3; c++) {
            T0[c] = J00*R[0][c] + J02*R[2][c];
            T1[c] = J11*R[1][c] + J12*R[2][c];
        }
        float S[3][3];
        #pragma unroll
        for (int r = 0; r < 3; r++)
            #pragma unroll
            for (int c = 0; c < 3; c++)
                S[r][c] = cov[i*9 + r*3 + c];
        float v0[3], v1[3];
        #pragma unroll
        for (int r = 0; r < 3; r++) {
            v0[r] = S[r][0]*T0[0] + S[r][1]*T0[1] + S[r][2]*T0[2];
            v1[r] = S[r][0]*T1[0] + S[r][1]*T1[1] + S[r][2]*T1[2];
        }
        const float a  = T0[0]*v0[0] + T0[1]*v0[1] + T0[2]*v0[2] + 0.3f;
        const float b  = T1[0]*v0[0] + T1[1]*v0[1] + T1[2]*v0[2];
        const float d  = T1[0]*v1[0] + T1[1]*v1[1] + T1[2]*v1[2] + 0.3f;

        const float det = a*d - b*b;
        const float tr  = a + d;
        const float lam = 0.5f * (tr + sqrtf(fmaxf(tr*tr - 4.0f*det, 0.0f)));
        const float radf = 3.0f * sqrtf(fmaxf(lam, 1e-8f));

        if (is_block0)
            out[5*HW + i] = visible ? radf : 0.0f;

        if (visible) {
            // bbox (exact reference floor(clip()) semantics)
            const float rad = fmaxf(radf, 1.0f);
            const float xlo = floorf(fminf(fmaxf(mx - rad,        0.0f), (float)IW));
            const float xhi = floorf(fminf(fmaxf(mx + rad + 1.0f, 0.0f), (float)IW));
            const float ylo = floorf(fminf(fmaxf(my - rad,        0.0f), (float)IH));
            const float yhi = floorf(fminf(fmaxf(my + rad + 1.0f, 0.0f), (float)IH));

            // tile overlap test
            if (xhi > ftx0 && xlo <= ftx1 && yhi > fty0 && ylo <= fty1) {
                // conic
                const float detc = fmaxf(det, 1e-10f);
                const float i00 =  d / detc;
                const float i01 = -b / detc;
                const float i11 =  a / detc;

                // view direction + SH->RGB (only for tile hits)
                float vx = px - cpx, vy = py - cpy, vz = pz - cpz;
                const float inv_nrm =
                    1.0f / fmaxf(sqrtf(vx*vx + vy*vy + vz*vz), 1e-12f);
                vx *= inv_nrm; vy *= inv_nrm; vz *= inv_nrm;

                const float xx = vx*vx, yy = vy*vy, zz = vz*vz;
                const float xy_ = vx*vy, yz_ = vy*vz, xz_ = vx*vz;
                float B[16];
                B[0]  = 0.28209479177387814f;
                B[1]  = -0.4886025119029199f * vy;
                B[2]  =  0.4886025119029199f * vz;
                B[3]  = -0.4886025119029199f * vx;
                B[4]  =  1.0925484305920792f * xy_;
                B[5]  = -1.0925484305920792f * yz_;
                B[6]  =  0.31539156525252005f * (2.0f*zz - xx - yy);
                B[7]  = -1.0925484305920792f * xz_;
                B[8]  =  0.5462742152960396f * (xx - yy);
                B[9]  = -0.5900435899266435f * vy * (3.0f*xx - yy);
                B[10] =  2.890611442640554f  * xy_ * vz;
                B[11] = -0.4570457994644658f * vy * (4.0f*zz - xx - yy);
                B[12] =  0.3731763325901154f * vz * (2.0f*zz - 3.0f*xx - 3.0f*yy);
                B[13] = -0.4570457994644658f * vx * (4.0f*zz - xx - yy);
                B[14] =  1.445305721320277f  * vz * (xx - yy);
                B[15] = -0.5900435899266435f * vx * (xx - 3.0f*yy);

                float rgb[3];
                #pragma unroll
                for (int c = 0; c < 3; c++) {
                    float s = 0.0f;
                    #pragma unroll
                    for (int j = 0; j < 16; j++)
                        s += B[j] * feat[i*48 + j*3 + c];
                    rgb[c] = fminf(fmaxf(s + 0.5f, 0.0f), 1.0f);
                }

                const int pos = atomicAdd(&s_cnt, 1);
                float* dst = s_par[pos];
                dst[0] = mx;     dst[1] = my;     dst[2]  = i00;    dst[3]  = i01;
                dst[4] = i11;    dst[5] = opa[i]; dst[6]  = rgb[0]; dst[7]  = rgb[1];
                dst[8] = rgb[2]; dst[9] = depth;  dst[10] = (float)i; dst[11] = 0.0f;
                dst[12] = xlo;   dst[13] = xhi;   dst[14] = ylo;    dst[15] = yhi;
            }
        }
    }
    __syncthreads();

    // ---- Phase 2: stable rank sort of this tile's list by (depth, idx) ----
    const int n = s_cnt;
    if (tid < n) {
        const float dep = s_par[tid][9];
        const float id  = s_par[tid][10];
        int rank = 0;
        for (int j = 0; j < n; j++) {
            const float dj = s_par[j][9];
            const float ij = s_par[j][10];
            rank += (dj < dep) || ((dj == dep) && (ij < id));
        }
        s_ord[rank] = tid;
    }
    __syncthreads();

    // ---- Phase 3: per-pixel front-to-back compositing ----
    const float gx = (float)(tx0 + threadIdx.x);
    const float gy = (float)(ty0 + threadIdx.y);

    float T = 1.0f, c0 = 0.0f, c1 = 0.0f, c2 = 0.0f, dsum = 0.0f;

    for (int k = 0; k < n; k++) {
        const float4* p = (const float4*)s_par[s_ord[k]];  // broadcast reads
        const float4 bb = p[3];
        if (gx >= bb.x && gx < bb.y && gy >= bb.z && gy < bb.w) {
            const float4 a0 = p[0];   // mx,my,i00,i01
            const float4 a1 = p[1];   // i11,op,r,g
            const float4 a2 = p[2];   // b,dep,idx,pad
            const float dx = gx - a0.x;
            const float dy = gy - a0.y;
            const float maha = a0.z*dx*dx + 2.0f*a0.w*dx*dy + a1.x*dy*dy;
            const float w = __expf(-0.5f * maha);
            const float alpha = fminf(a1.y * w, 0.99f);
            const float tc = T * alpha;
            c0   += tc * a1.z;
            c1   += tc * a1.w;
            c2   += tc * a2.x;
            dsum += tc * a2.y;
            T *= (1.0f - alpha);
            if (T < 1e-7f) break;
        }
    }

    const int idx = (ty0 + threadIdx.y) * IW + (tx0 + threadIdx.x);
    out[0*HW + idx] = c0 + bg[0] * T;
    out[1*HW + idx] = c1 + bg[1] * T;
    out[2*HW + idx] = c2 + bg[2] * T;
    out[3*HW + idx] = dsum;
    out[4*HW + idx] = 1.0f - T;
}

extern "C" void kernel_launch(void* const* d_in, const int* in_sizes, int n_in,
                              void* d_out, int out_size)
{
    const float* xyz  = (const float*)d_in[0];
    const float* opa  = (const float*)d_in[1];
    const float* feat = (const float*)d_in[2];
    const float* cov  = (const float*)d_in[3];
    const float* Km   = (const float*)d_in[4];
    const float* w2c  = (const float*)d_in[5];
    const float* bg   = (const float*)d_in[6];
    float* out = (float*)d_out;

    dim3 grid(IW/TW, IH/TH);   // 8 x 16 = 128 blocks (single wave on 148 SMs)
    dim3 block(TW, TH);        // 512 threads
    fused_render_kernel<<<grid, block>>>(xyz, opa, feat, cov, Km, w2c, bg, out);
}